// round 11
// baseline (speedup 1.0000x reference)
#include <cuda_runtime.h>
#include <cuda_fp16.h>
#include <math.h>

// Levels: RES = {128, 256, 512, 1024}, C=4 channels, 3 planes per level.
//
// Plane storage: fp16 "pair table" per (level, plane), lc-prefolded:
//   P[ye][s] (16 bytes) = { texel(y=ye-1, x=s-1) c0..c3, texel(y=ye-1, x=s) c0..c3 }
//   ye in [0, R+1], s in [0, R]; border rows/cols are zeros; every texel is
//   pre-multiplied by linec[l][p][c].
// A bilinear sample at (ix,iy) = two 16B loads: P[iy+1][ix+1], P[iy+2][ix+1].
// Total table = ~67MB -> L2-resident. Output is written with __stcs
// (evict-first) so the 201MB stream does not thrash the table.
#define NLEV 4

// texel pairs per level: 3*(R+2)*(R+1) -> 50310, 198918, 791046, 3154950 ; total 4195224 (~67MB)
__device__ __align__(16) uint4 g_pairs[4195224];
__device__ __align__(16) float g_linec[48];  // [l][p][c]

__constant__ int   c_lvloff[NLEV]   = {0, 50310, 249228, 1040274};       // pair offsets
__constant__ int   c_rowpitch[NLEV] = {129, 257, 513, 1025};             // R+1
__constant__ float c_halfR[NLEV]    = {64.f, 128.f, 256.f, 512.f};

// per-sample (s = l*3+p) base offsets: lvloff[l] + p*(R+2)*(R+1)
__constant__ int c_sbase[12] = {
    0,       16770,   33540,
    50310,   116616,  182922,
    249228,  512910,  776592,
    1040274, 2091924, 3143574};

// bit-reinterpret helpers (no-op in SASS)
__device__ __forceinline__ unsigned int h2_as_u32(__half2 h) {
    return *reinterpret_cast<unsigned int*>(&h);
}
__device__ __forceinline__ __half2 u32_as_h2(unsigned int u) {
    return *reinterpret_cast<__half2*>(&u);
}

// ---------------------------------------------------------------------------
// Line constants: triline grid_sample degenerates to
//   linec[l,p,c] = 0.5*(tl[p,c,R/2-1,0] + tl[p,c,R/2,0])
// Runs BEFORE the pair-table builders, which fold these into the texels.
// ---------------------------------------------------------------------------
__global__ void linec_kernel(const float* __restrict__ t0, const float* __restrict__ t1,
                             const float* __restrict__ t2, const float* __restrict__ t3) {
    int i = threadIdx.x;
    if (i >= 48) return;
    const int res[NLEV] = {128, 256, 512, 1024};
    int l  = i / 12;
    int pc = i % 12;            // p*4 + c
    const float* t = (l == 0) ? t0 : (l == 1) ? t1 : (l == 2) ? t2 : t3;
    int r = res[l];
    g_linec[i] = 0.5f * (t[pc * r + r / 2 - 1] + t[pc * r + r / 2]);
}

// ---------------------------------------------------------------------------
// Build fp16 pair table with zero borders, lc-prefolded.
// grid: ( ceil((R+1)/256), R+2, 3 ) ; thread.x = s, block.y = ye, block.z = p
// ---------------------------------------------------------------------------
__global__ void pair_kernel(const float* __restrict__ in, int R, int lvl) {
    int s  = blockIdx.x * blockDim.x + threadIdx.x;      // 0..R
    if (s > R) return;
    int ye = blockIdx.y;                                 // 0..R+1
    int p  = blockIdx.z;
    int y  = ye - 1;
    int rr = R * R;
    bool yok = (y >= 0) && (y < R);
    bool lok = yok && (s >= 1);
    bool hok = yok && (s < R);
    const float* bp = in + (size_t)(p * 4) * rr + (size_t)y * R;
    const float* lc = g_linec + lvl * 12 + p * 4;

    __half h[8];
#pragma unroll
    for (int c = 0; c < 4; c++) {
        float l_ = lc[c];
        float lv = lok ? __ldg(bp + (size_t)c * rr + (s - 1)) * l_ : 0.f;
        float hv = hok ? __ldg(bp + (size_t)c * rr + s)       * l_ : 0.f;
        h[c]     = __float2half_rn(lv);
        h[4 + c] = __float2half_rn(hv);
    }
    uint4 t;
    t.x = h2_as_u32(__halves2half2(h[0], h[1]));   // lo texel c0,c1
    t.y = h2_as_u32(__halves2half2(h[2], h[3]));   // lo texel c2,c3
    t.z = h2_as_u32(__halves2half2(h[4], h[5]));   // hi texel c0,c1
    t.w = h2_as_u32(__halves2half2(h[6], h[7]));   // hi texel c2,c3
    int rp = R + 1;
    g_pairs[c_lvloff[lvl] + p * (R + 2) * rp + ye * rp + s] = t;
}

// ---------------------------------------------------------------------------
// Main kernel: one thread per (point, level); 3 plane samples per thread.
// Writes 3 consecutive float4 with __stcs (streaming, evict-first).
// ---------------------------------------------------------------------------
__global__ __launch_bounds__(256)
void enc_kernel(const float* __restrict__ x, float* __restrict__ out, int N) {
    int tid   = blockIdx.x * blockDim.x + threadIdx.x;
    int point = tid >> 2;
    if (point >= N) return;
    int l = tid & 3;

    const float* xp = x + 3 * (size_t)point;
    float px = fmaf(2.f, __ldg(xp + 0), -1.f);
    float py = fmaf(2.f, __ldg(xp + 1), -1.f);
    float pz = fmaf(2.f, __ldg(xp + 2), -1.f);

    // plane p: (u=width, v=height) per reference projections (xz), (yx), (zy)
    float uu[3] = {px, py, pz};
    float vv[3] = {pz, px, py};
    float wl[3] = {fmaf(-0.5f, fabsf(px), 1.f),
                   fmaf(-0.5f, fabsf(py), 1.f),
                   fmaf(-0.5f, fabsf(pz), 1.f)};

    float hR = c_halfR[l];
    int   rp = c_rowpitch[l];

    float4* o4 = reinterpret_cast<float4*>(out) + (size_t)point * 12 + l * 3;

#pragma unroll
    for (int p = 0; p < 3; p++) {
        float fx = fmaf(uu[p], hR, hR - 0.5f);
        float fy = fmaf(vv[p], hR, hR - 0.5f);
        float fx0 = floorf(fx), fy0 = floorf(fy);
        float wx = fx - fx0,   wy = fy - fy0;
        int ix = (int)fx0, iy = (int)fy0;

        int idx = c_sbase[l * 3 + p] + (iy + 1) * rp + (ix + 1);
        uint4 t0 = __ldg(&g_pairs[idx]);        // row y0: lo/hi texels
        uint4 t1 = __ldg(&g_pairs[idx + rp]);   // row y1

        __half2 wx2 = __float2half2_rn(wx);
        __half2 wy2 = __float2half2_rn(wy);

        __half2 a01 = u32_as_h2(t0.x), a23 = u32_as_h2(t0.y);   // y0,x0
        __half2 b01 = u32_as_h2(t0.z), b23 = u32_as_h2(t0.w);   // y0,x1
        __half2 c01 = u32_as_h2(t1.x), c23 = u32_as_h2(t1.y);   // y1,x0
        __half2 d01 = u32_as_h2(t1.z), d23 = u32_as_h2(t1.w);   // y1,x1

        // x-lerp both rows, then y-lerp (fp16); lc already folded into texels
        __half2 r01 = __hfma2(__hsub2(b01, a01), wx2, a01);
        __half2 r23 = __hfma2(__hsub2(b23, a23), wx2, a23);
        __half2 s01 = __hfma2(__hsub2(d01, c01), wx2, c01);
        __half2 s23 = __hfma2(__hsub2(d23, c23), wx2, c23);
        __half2 v01 = __hfma2(__hsub2(s01, r01), wy2, r01);
        __half2 v23 = __hfma2(__hsub2(s23, r23), wy2, r23);

        float2 f01 = __half22float2(v01);
        float2 f23 = __half22float2(v23);

        float s = wl[p];
        float4 r;
        r.x = f01.x * s;
        r.y = f01.y * s;
        r.z = f23.x * s;
        r.w = f23.y * s;
        __stcs(&o4[p], r);   // streaming store: don't thrash the L2-resident table
    }
}

// ---------------------------------------------------------------------------
// Launch: identify inputs by size (robust to metadata ordering)
// ---------------------------------------------------------------------------
extern "C" void kernel_launch(void* const* d_in, const int* in_sizes, int n_in,
                              void* d_out, int out_size) {
    const int res[NLEV] = {128, 256, 512, 1024};

    // triplane_l : 12*R*R = 196608, 786432, 3145728, 12582912
    // triline_l  : 12*R   = 1536, 3072, 6144, 12288
    // x          : 3*N    = 3145728 (ambiguous with triplane_2)
    int tp_idx[NLEV] = {-1, -1, -1, -1};
    int tl_idx[NLEV] = {-1, -1, -1, -1};
    int amb[2]; int n_amb = 0;
    int x_idx = -1;

    for (int i = 0; i < n_in; i++) {
        int s = in_sizes[i];
        if      (s == 196608)   tp_idx[0] = i;
        else if (s == 786432)   tp_idx[1] = i;
        else if (s == 12582912) tp_idx[3] = i;
        else if (s == 1536)     tl_idx[0] = i;
        else if (s == 3072)     tl_idx[1] = i;
        else if (s == 6144)     tl_idx[2] = i;
        else if (s == 12288)    tl_idx[3] = i;
        else if (s == 3145728)  { if (n_amb < 2) amb[n_amb++] = i; }
        else if (x_idx < 0)     x_idx = i;
    }
    if (n_amb == 1) {
        tp_idx[2] = amb[0];
    } else if (n_amb == 2) {
        // triplane_0..3 occupy contiguous ascending indices in either ordering
        int a = amb[0], b = amb[1];
        if (a > tp_idx[1] && a < tp_idx[3]) { tp_idx[2] = a; x_idx = b; }
        else                                { tp_idx[2] = b; x_idx = a; }
    }
    if (x_idx < 0) x_idx = 0;

    const float* x = (const float*)d_in[x_idx];
    int N = in_sizes[x_idx] / 3;

    // 1) line constants first (folded into pair tables)
    linec_kernel<<<1, 64>>>((const float*)d_in[tl_idx[0]], (const float*)d_in[tl_idx[1]],
                            (const float*)d_in[tl_idx[2]], (const float*)d_in[tl_idx[3]]);

    // 2) build fp16 pair tables (zero-bordered, lc-prefolded)
    for (int l = 0; l < NLEV; l++) {
        const float* tp = (const float*)d_in[tp_idx[l]];
        int R = res[l];
        dim3 grid((R + 1 + 255) / 256, R + 2, 3);
        pair_kernel<<<grid, 256>>>(tp, R, l);
    }

    // 3) main pass: 4 threads per point (one per level)
    long long threads = 4LL * N;
    enc_kernel<<<(int)((threads + 255) / 256), 256>>>(x, (float*)d_out, N);
}